// round 1
// baseline (speedup 1.0000x reference)
#include <cuda_runtime.h>
#include <cuda_bf16.h>

// Conv4D: x(8,16,32,24,24,24) NCLDHW  *  W(32,16,3,3,3,3) OILDHW -> out(8,32,30,22,22,22)
// out += 3*b (bias applied l_k times in the reference).
//
// Strategy: 1 CTA per (n, l_out, d_out). Loop over (l_k, d_k) (9 slabs):
//   stage x[n, :, l_out+l_k, d_out+d_k, :, :] (16x24x24 = 36KB) and the
//   W slice re-laid-out as ws[ci*9+hk*3+wk][cout] (144x32 = 18KB) in smem.
// 256 threads = 4 cout-groups (8 couts each) x 64 position-threads
// (8 positions each, strided by 64 over the 22x22=484 spatial tile).
// Accumulators packed as f32x2 pairs -> fma.rn.f32x2 (FFMA2) doubles fp32 rate.

#define CIN   16
#define COUT  32
#define L_IN  32
#define S_IN  24
#define L_OUTD 30
#define S_OUTD 22
#define SLAB_F (CIN * S_IN * S_IN)      // 9216 floats
#define WSL_F  (CIN * 9 * COUT)         // 4608 floats
#define SMEM_BYTES ((SLAB_F + WSL_F) * 4)  // 55296

extern __shared__ float smem_dyn[];

__global__ __launch_bounds__(256, 2)
void conv4d_kernel(const float* __restrict__ x,
                   const float* __restrict__ W,
                   const float* __restrict__ b,
                   float* __restrict__ out)
{
    const int d_out = blockIdx.x;   // 0..21
    const int l_out = blockIdx.y;   // 0..29
    const int n     = blockIdx.z;   // 0..7
    const int tid   = threadIdx.x;
    const int cg    = tid >> 6;     // cout group 0..3 (8 couts each)
    const int pt    = tid & 63;     // position thread 0..63

    float* xs = smem_dyn;           // [CIN][24][24]
    float* ws = smem_dyn + SLAB_F;  // [144][32]  (r = ci*9+hk*3+wk, then cout)

    // Per-i spatial position (strided coverage of 484 positions by 64 threads)
    int off[8];
    #pragma unroll
    for (int i = 0; i < 8; i++) {
        int pos = pt + i * 64;
        int h = pos / 22;
        int w = pos - h * 22;
        off[i] = (pos < 484) ? (h * S_IN + w) : 0;   // clamp inactive to 0
    }

    // 8 positions x 4 f32x2 pairs (= 8 couts) accumulators
    unsigned long long acc[8][4];
    #pragma unroll
    for (int i = 0; i < 8; i++)
        #pragma unroll
        for (int c = 0; c < 4; c++)
            acc[i][c] = 0ULL;

    for (int lk = 0; lk < 3; lk++) {
        const int l_in = l_out + lk;
        for (int dk = 0; dk < 3; dk++) {
            const int d_in = d_out + dk;
            __syncthreads();   // protect previous iteration's smem reads

            // ---- stage x slab: 2304 float4 loads, per-cin contiguous 576-float chunks
            {
                #pragma unroll
                for (int j = 0; j < 9; j++) {
                    int v = tid + j * 256;            // 0..2303
                    int c = v / 144;                  // 144 float4 per cin
                    int within = v - c * 144;
                    const float4* src = reinterpret_cast<const float4*>(
                        x + (size_t)((((n * CIN + c) * L_IN + l_in) * S_IN + d_in)) * (S_IN * S_IN))
                        + within;
                    reinterpret_cast<float4*>(xs)[v] = *src;
                }
            }
            // ---- stage W slice for this (lk,dk): ws[r*32+co]
            {
                #pragma unroll
                for (int j = 0; j < 18; j++) {
                    int e  = tid + j * 256;           // 0..4607, e = r*32 + co
                    int co = e & 31;
                    int r  = e >> 5;                  // ci*9 + hk*3 + wk
                    int ci = r / 9;
                    int t  = r - ci * 9;
                    int hk = t / 3;
                    int wk = t - hk * 3;
                    ws[e] = W[(((((co * CIN + ci) * 3 + lk) * 3 + dk) * 3 + hk) * 3 + wk)];
                }
            }
            __syncthreads();

            // ---- mainloop: 16 cin x 3x3 taps
            for (int ci = 0; ci < CIN; ci++) {
                const float* xb = xs + ci * (S_IN * S_IN);
                const float* wb8 = ws + (ci * 9) * 32 + cg * 8;
                #pragma unroll
                for (int hk = 0; hk < 3; hk++) {
                    #pragma unroll
                    for (int wk = 0; wk < 3; wk++) {
                        const int r = hk * 3 + wk;
                        float4 wa = *reinterpret_cast<const float4*>(wb8 + r * 32);
                        float4 wbv = *reinterpret_cast<const float4*>(wb8 + r * 32 + 4);
                        unsigned long long w2[4];
                        asm("mov.b64 %0, {%1,%2};" : "=l"(w2[0]) : "f"(wa.x),  "f"(wa.y));
                        asm("mov.b64 %0, {%1,%2};" : "=l"(w2[1]) : "f"(wa.z),  "f"(wa.w));
                        asm("mov.b64 %0, {%1,%2};" : "=l"(w2[2]) : "f"(wbv.x), "f"(wbv.y));
                        asm("mov.b64 %0, {%1,%2};" : "=l"(w2[3]) : "f"(wbv.z), "f"(wbv.w));
                        const int xoffc = hk * S_IN + wk;
                        #pragma unroll
                        for (int i = 0; i < 8; i++) {
                            float xv = xb[off[i] + xoffc];
                            unsigned long long xx;
                            asm("mov.b64 %0, {%1,%1};" : "=l"(xx) : "f"(xv));
                            #pragma unroll
                            for (int c = 0; c < 4; c++)
                                asm("fma.rn.f32x2 %0, %1, %2, %0;"
                                    : "+l"(acc[i][c]) : "l"(xx), "l"(w2[c]));
                        }
                    }
                }
            }
        }
    }

    // ---- epilogue: unpack, add 3*b, store
    #pragma unroll
    for (int i = 0; i < 8; i++) {
        int pos = pt + i * 64;
        if (pos >= 484) continue;
        int h = pos / 22;
        int w = pos - h * 22;
        #pragma unroll
        for (int c2 = 0; c2 < 4; c2++) {
            float lo, hi;
            asm("mov.b64 {%0,%1}, %2;" : "=f"(lo), "=f"(hi) : "l"(acc[i][c2]));
            int co0 = cg * 8 + 2 * c2;
            size_t o0 = ((((size_t)(n * COUT + co0) * L_OUTD + l_out) * S_OUTD + d_out) * S_OUTD + h) * S_OUTD + w;
            size_t o1 = o0 + (size_t)L_OUTD * S_OUTD * S_OUTD * S_OUTD;  // next cout
            out[o0] = lo + 3.0f * b[co0];
            out[o1] = hi + 3.0f * b[co0 + 1];
        }
    }
}

extern "C" void kernel_launch(void* const* d_in, const int* in_sizes, int n_in,
                              void* d_out, int out_size)
{
    const float* x = (const float*)d_in[0];
    const float* W = (const float*)d_in[1];
    const float* b = (const float*)d_in[2];
    float* out = (float*)d_out;

    cudaFuncSetAttribute(conv4d_kernel,
                         cudaFuncAttributeMaxDynamicSharedMemorySize, SMEM_BYTES);

    dim3 grid(S_OUTD, L_OUTD, 8);   // (d_out, l_out, n) = (22, 30, 8)
    conv4d_kernel<<<grid, 256, SMEM_BYTES>>>(x, W, b, out);
}

// round 4
// speedup vs baseline: 2.1732x; 2.1732x over previous
#include <cuda_runtime.h>
#include <cstdint>

// Conv4D via mma.sync tf32 (portable sm_80+ PTX; tcgen05 is unavailable:
// harness PTX target is compute_103 without the 'a' feature suffix).
//
// x(8,16,32,24,24,24) NCLDHW * W(32,16,3,3,3,3) OILDHW -> out(8,32,30,22,22,22)
// out += 3*b.
//
// CTA = (n, l_out, d_out). Implicit GEMM:
//   D[m = flat(h,w) over 24x24 grid, padded to 640][n = cout 32]
// K-loop: 9 (lk,dk) slabs x 9 (hk,wk) taps x 2 ci-octets. Accumulate in regs.
// A fragments read from x slab in smem (rows padded to 712 floats,
// (8c+g)%32 bank-unique); B from W tile (rows padded to 40).
// Staging via cp.async, double-buffered across slabs.

#define XROW 712
#define XBUF_BYTES (16 * XROW * 4)          // 45568
#define WROW 40
#define WBUF_BYTES (9 * 16 * WROW * 4)      // 23040
#define OFF_X0 0
#define OFF_X1 XBUF_BYTES
#define OFF_W0 (2 * XBUF_BYTES)
#define OFF_W1 (2 * XBUF_BYTES + WBUF_BYTES)
#define OFF_BS (2 * XBUF_BYTES + 2 * WBUF_BYTES)
#define SMEM_TOTAL (OFF_BS + 128)           // 137472 - 128... = 137344

#define CI_STRIDE 442368                    // 32*24*24*24 floats between ci planes
#define L_STRIDE  13824                     // 24*24*24
#define OUT_CO_STRIDE 319440                // 30*22*22*22

static __device__ __forceinline__ uint32_t s2u(const void* p) {
    uint32_t a;
    asm("{ .reg .u64 t; cvta.to.shared.u64 t, %1; cvt.u32.u64 %0, t; }" : "=r"(a) : "l"(p));
    return a;
}
static __device__ __forceinline__ uint32_t tf32rn(float f) {
    uint32_t o;
    asm("cvt.rna.tf32.f32 %0, %1;" : "=r"(o) : "f"(f));
    return o;
}
static __device__ __forceinline__ void cp16(uint32_t dst, const void* src) {
    asm volatile("cp.async.cg.shared.global [%0], [%1], 16;" :: "r"(dst), "l"(src) : "memory");
}
static __device__ __forceinline__ void cp4(uint32_t dst, const void* src) {
    asm volatile("cp.async.ca.shared.global [%0], [%1], 4;" :: "r"(dst), "l"(src) : "memory");
}

#define MMA_TF32(d, a0, a1, a2, a3, b0, b1) \
    asm volatile("mma.sync.aligned.m16n8k8.row.col.f32.tf32.tf32.f32 " \
        "{%0,%1,%2,%3}, {%4,%5,%6,%7}, {%8,%9}, {%0,%1,%2,%3};" \
        : "+f"((d)[0]), "+f"((d)[1]), "+f"((d)[2]), "+f"((d)[3]) \
        : "r"(a0), "r"(a1), "r"(a2), "r"(a3), "r"(b0), "r"(b1))

extern __shared__ char smem[];

__global__ __launch_bounds__(256)
void conv4d_mma_kernel(const float* __restrict__ x,
                       const float* __restrict__ W,
                       const float* __restrict__ b,
                       float* __restrict__ out)
{
    const int d_out = blockIdx.x;   // 0..21
    const int l_out = blockIdx.y;   // 0..29
    const int n     = blockIdx.z;   // 0..7
    const int tid   = threadIdx.x;
    const int wid   = tid >> 5;
    const int lid   = tid & 31;
    const int c     = lid & 3;      // k-quad within fragment
    const int g     = lid >> 2;     // group (row/col group)
    const uint32_t sb = s2u(smem);

    if (tid < 32) ((float*)(smem + OFF_BS))[tid] = 3.0f * b[tid];

    // ---- staging helpers (cp.async) ----
    auto stage = [&](int s) {
        const int lk = s / 3, dk = s - 3 * lk;
        const int l_in = l_out + lk;
        const int d_in = d_out + dk;
        const uint32_t xoff = sb + ((s & 1) ? OFF_X1 : OFF_X0);
        const uint32_t woff = sb + ((s & 1) ? OFF_W1 : OFF_W0);
        const float* xb = x + ((size_t)(n * 16) * 32 + l_in) * L_STRIDE + d_in * 576;
        #pragma unroll
        for (int j = 0; j < 9; j++) {
            int it = tid + j * 256;          // 0..2303
            int ci = it / 144;               // 144 16B-chunks per ci row (576 floats)
            int ch = it - ci * 144;
            cp16(xoff + (uint32_t)(ci * (XROW * 4) + ch * 16),
                 xb + (size_t)ci * CI_STRIDE + ch * 4);
        }
        #pragma unroll
        for (int j = 0; j < 18; j++) {
            int e   = tid + j * 256;         // 0..4607
            int tap = e >> 9;
            int ci  = (e >> 5) & 15;
            int co  = e & 31;
            int hk  = tap / 3, wk = tap - 3 * hk;
            cp4(woff + (uint32_t)(((tap * 16 + ci) * WROW + co) * 4),
                W + (size_t)(co * 16 + ci) * 81 + lk * 27 + dk * 9 + hk * 3 + wk);
        }
        asm volatile("cp.async.commit_group;" ::: "memory");
    };

    float acc[5][4][4];
    #pragma unroll
    for (int mt = 0; mt < 5; mt++)
        #pragma unroll
        for (int nt = 0; nt < 4; nt++)
            #pragma unroll
            for (int q = 0; q < 4; q++)
                acc[mt][nt][q] = 0.0f;

    stage(0);

    for (int s = 0; s < 9; s++) {
        if (s < 8) {
            stage(s + 1);
            asm volatile("cp.async.wait_group 1;" ::: "memory");
        } else {
            asm volatile("cp.async.wait_group 0;" ::: "memory");
        }
        __syncthreads();

        const float* xs = (const float*)(smem + ((s & 1) ? OFF_X1 : OFF_X0));
        const float* ws = (const float*)(smem + ((s & 1) ? OFF_W1 : OFF_W0));

        for (int tap = 0; tap < 9; tap++) {
            const int hk = tap / 3;
            const int tapoff = hk * 24 + (tap - 3 * hk);
            #pragma unroll
            for (int kc = 0; kc < 2; kc++) {
                // B fragments: B[k][n], k = kc*8 + c (+4), n = nt*8 + g
                const float* wrow = ws + (tap * 16 + kc * 8 + c) * WROW + g;
                uint32_t breg[4][2];
                #pragma unroll
                for (int nt = 0; nt < 4; nt++) {
                    breg[nt][0] = tf32rn(wrow[nt * 8]);
                    breg[nt][1] = tf32rn(wrow[4 * WROW + nt * 8]);
                }
                // A fragments per m-tile
                const float* xrow = xs + (kc * 8 + c) * XROW + g + tapoff;
                #pragma unroll
                for (int mt = 0; mt < 5; mt++) {
                    const int m0 = (wid * 5 + mt) * 16;
                    uint32_t a0 = tf32rn(xrow[m0]);
                    uint32_t a1 = tf32rn(xrow[m0 + 8]);
                    uint32_t a2 = tf32rn(xrow[4 * XROW + m0]);
                    uint32_t a3 = tf32rn(xrow[4 * XROW + m0 + 8]);
                    #pragma unroll
                    for (int nt = 0; nt < 4; nt++)
                        MMA_TF32(acc[mt][nt], a0, a1, a2, a3, breg[nt][0], breg[nt][1]);
                }
            }
        }
        __syncthreads();   // compute done before next stage overwrites buffers
    }

    // ---- epilogue: D row = groupID (+8), col = 2c (+1) ----
    const float* bs = (const float*)(smem + OFF_BS);
    const int spat = l_out * 10648 + d_out * 484;   // 10648 = 22*484
    #pragma unroll
    for (int mt = 0; mt < 5; mt++) {
        const int mb = (wid * 5 + mt) * 16 + g;
        #pragma unroll
        for (int hm = 0; hm < 2; hm++) {
            int m = mb + 8 * hm;
            int h = m / 24;
            int w = m - 24 * h;
            if (h < 22 && w < 22) {
                size_t pos = (size_t)spat + h * 22 + w;
                #pragma unroll
                for (int nt = 0; nt < 4; nt++) {
                    #pragma unroll
                    for (int hc = 0; hc < 2; hc++) {
                        int co = nt * 8 + 2 * c + hc;
                        out[(size_t)(n * 32 + co) * OUT_CO_STRIDE + pos] =
                            acc[mt][nt][hm * 2 + hc] + bs[co];
                    }
                }
            }
        }
    }
}

extern "C" void kernel_launch(void* const* d_in, const int* in_sizes, int n_in,
                              void* d_out, int out_size)
{
    const float* x = (const float*)d_in[0];
    const float* W = (const float*)d_in[1];
    const float* b = (const float*)d_in[2];
    float* out = (float*)d_out;

    cudaFuncSetAttribute(conv4d_mma_kernel,
                         cudaFuncAttributeMaxDynamicSharedMemorySize, SMEM_TOTAL);

    dim3 grid(22, 30, 8);   // (d_out, l_out, n)
    conv4d_mma_kernel<<<grid, 256, SMEM_TOTAL>>>(x, W, b, out);
}